// round 12
// baseline (speedup 1.0000x reference)
#include <cuda_runtime.h>
#include <cstdint>

#define D          512
#define ROW_BYTES  2048
#define MARGIN     1.0f
#define NSTAGE     2
#define PIPE_WARPS 2                  // warps 0-1: bulk-copy pipeline
#define TPB        128                // 4 warps
#define GRID       512
#define PER_CTA    32                 // 512 * 32 = 16384 triplets
#define STAGE_TX   (3 * ROW_BYTES)

__global__ void zero_out_kernel(float* out) {
    if (threadIdx.x == 0) out[0] = 0.0f;
}

__device__ __forceinline__ uint32_t smem_u32(const void* p) {
    return (uint32_t)__cvta_generic_to_shared(p);
}
__device__ __forceinline__ void mbar_init(uint32_t addr, uint32_t count) {
    asm volatile("mbarrier.init.shared::cta.b64 [%0], %1;" :: "r"(addr), "r"(count) : "memory");
}
__device__ __forceinline__ void mbar_expect_tx(uint32_t addr, uint32_t bytes) {
    asm volatile("mbarrier.arrive.expect_tx.shared::cta.b64 _, [%0], %1;"
                 :: "r"(addr), "r"(bytes) : "memory");
}
__device__ __forceinline__ void mbar_wait(uint32_t addr, uint32_t parity) {
    uint32_t done = 0;
    while (!done) {
        asm volatile(
            "{\n\t.reg .pred p;\n\t"
            "mbarrier.try_wait.parity.acquire.cta.shared::cta.b64 p, [%1], %2, 0x989680;\n\t"
            "selp.b32 %0, 1, 0, p;\n\t}"
            : "=r"(done) : "r"(addr), "r"(parity) : "memory");
    }
}
__device__ __forceinline__ void bulk_g2s(uint32_t dst_smem, const void* src_gmem,
                                         uint32_t bytes, uint32_t mbar) {
    asm volatile(
        "cp.async.bulk.shared::cluster.global.mbarrier::complete_tx::bytes "
        "[%0], [%1], %2, [%3];"
        :: "r"(dst_smem), "l"(src_gmem), "r"(bytes), "r"(mbar) : "memory");
}
__device__ __forceinline__ void fma2(unsigned long long& acc,
                                     unsigned long long a,
                                     unsigned long long b) {
    asm("fma.rn.f32x2 %0, %1, %2, %0;" : "+l"(acc) : "l"(a), "l"(b));
}
__device__ __forceinline__ float lo_f(unsigned long long v) {
    return __uint_as_float((unsigned)(v & 0xFFFFFFFFull));
}
__device__ __forceinline__ float hi_f(unsigned long long v) {
    return __uint_as_float((unsigned)(v >> 32));
}

// Combine the four packed accumulators into the expanded difference:
// d_ap - d_an = Sp - Sn - 2*Sap + 2*San
__device__ __forceinline__ float combine4(unsigned long long Sp, unsigned long long Sn,
                                          unsigned long long Sap, unsigned long long San) {
    return (lo_f(Sp) + hi_f(Sp)) - (lo_f(Sn) + hi_f(Sn))
         + 2.0f * ((lo_f(San) + hi_f(San)) - (lo_f(Sap) + hi_f(Sap)));
}

__global__ void __launch_bounds__(TPB)
triplet_hybrid_kernel(const float* __restrict__ batch,
                      const int* __restrict__ triplets,
                      float* __restrict__ out) {
    // Dynamic smem: rows[PIPE_WARPS][NSTAGE][3][D] floats = 24576 bytes.
    extern __shared__ __align__(1024) float rows[];
    __shared__ __align__(8) unsigned long long full_bar[PIPE_WARPS][NSTAGE];
    __shared__ int   idx_s[PER_CTA * 3];
    __shared__ int   ctr;
    __shared__ float warp_part[TPB / 32];

    const int tid  = threadIdx.x;
    const int lane = tid & 31;
    const int wid  = tid >> 5;

    for (int k = tid; k < PER_CTA * 3; k += TPB)
        idx_s[k] = triplets[blockIdx.x * (PER_CTA * 3) + k];
    if (tid == 0) ctr = 0;
    if (tid < PIPE_WARPS * NSTAGE)
        mbar_init(smem_u32(&full_bar[tid >> 1][tid & 1]), 1);
    if (tid == 0)
        asm volatile("fence.proxy.async.shared::cta;" ::: "memory");
    __syncthreads();

    // Warp-uniform dynamic claim from the shared counter.
    auto claim = [&]() -> int {
        int t = 0;
        if (lane == 0) t = atomicAdd(&ctr, 1);
        return __shfl_sync(0xFFFFFFFFu, t, 0);
    };

    #define SLOT(w, s, r) (rows + (((w) * NSTAGE + (s)) * 3 + (r)) * D)

    float acc = 0.0f;  // lane-0 accumulator

    if (wid < PIPE_WARPS) {
        // ── Bulk-copy pipeline path (TMA in-flight pool) ──
        int tt[NSTAGE];
        int ph[NSTAGE] = {0, 0};
        tt[0] = claim();
        tt[1] = claim();
        if (lane == 0) {
            #pragma unroll
            for (int s = 0; s < NSTAGE; s++) {
                if (tt[s] < PER_CTA) {
                    const uint32_t fb = smem_u32(&full_bar[wid][s]);
                    mbar_expect_tx(fb, STAGE_TX);
                    #pragma unroll
                    for (int r = 0; r < 3; r++)
                        bulk_g2s(smem_u32(SLOT(wid, s, r)),
                                 batch + (size_t)idx_s[tt[s] * 3 + r] * D,
                                 ROW_BYTES, fb);
                }
            }
        }

        int s = 0;
        while (tt[0] < PER_CTA || tt[1] < PER_CTA) {
            if (tt[s] < PER_CTA) {
                mbar_wait(smem_u32(&full_bar[wid][s]), ph[s]);
                ph[s] ^= 1;

                const ulonglong2* A = reinterpret_cast<const ulonglong2*>(SLOT(wid, s, 0)) + lane;
                const ulonglong2* P = reinterpret_cast<const ulonglong2*>(SLOT(wid, s, 1)) + lane;
                const ulonglong2* N = reinterpret_cast<const ulonglong2*>(SLOT(wid, s, 2)) + lane;

                unsigned long long Sp = 0, Sn = 0, Sap = 0, San = 0;
                #pragma unroll
                for (int j = 0; j < 4; j++) {
                    const ulonglong2 a = A[j * 32];
                    const ulonglong2 p = P[j * 32];
                    const ulonglong2 n = N[j * 32];
                    fma2(Sp,  p.x, p.x);  fma2(Sp,  p.y, p.y);
                    fma2(Sn,  n.x, n.x);  fma2(Sn,  n.y, n.y);
                    fma2(Sap, a.x, p.x);  fma2(Sap, a.y, p.y);
                    fma2(San, a.x, n.x);  fma2(San, a.y, n.y);
                }
                float v = combine4(Sp, Sn, Sap, San);
                #pragma unroll
                for (int off = 16; off > 0; off >>= 1)
                    v += __shfl_down_sync(0xFFFFFFFFu, v, off);
                if (lane == 0) acc += fmaxf(v + MARGIN, 0.0f);

                __syncwarp();
                const int nt = claim();
                tt[s] = nt;
                if (nt < PER_CTA && lane == 0) {
                    const uint32_t fb = smem_u32(&full_bar[wid][s]);
                    mbar_expect_tx(fb, STAGE_TX);
                    #pragma unroll
                    for (int r = 0; r < 3; r++)
                        bulk_g2s(smem_u32(SLOT(wid, s, r)),
                                 batch + (size_t)idx_s[nt * 3 + r] * D,
                                 ROW_BYTES, fb);
                }
            }
            s ^= 1;
        }
    } else {
        // ── Direct LDG gather path (L1tex/MSHR pool) ──
        while (true) {
            const int t = claim();
            if (t >= PER_CTA) break;
            const int ia = idx_s[t * 3 + 0];
            const int ip = idx_s[t * 3 + 1];
            const int in = idx_s[t * 3 + 2];

            const ulonglong2* A = reinterpret_cast<const ulonglong2*>(batch + (size_t)ia * D) + lane;
            const ulonglong2* P = reinterpret_cast<const ulonglong2*>(batch + (size_t)ip * D) + lane;
            const ulonglong2* N = reinterpret_cast<const ulonglong2*>(batch + (size_t)in * D) + lane;

            unsigned long long Sp = 0, Sn = 0, Sap = 0, San = 0;
            #pragma unroll
            for (int j = 0; j < 4; j++) {
                const ulonglong2 a = A[j * 32];
                const ulonglong2 p = P[j * 32];
                const ulonglong2 n = N[j * 32];
                fma2(Sp,  p.x, p.x);  fma2(Sp,  p.y, p.y);
                fma2(Sn,  n.x, n.x);  fma2(Sn,  n.y, n.y);
                fma2(Sap, a.x, p.x);  fma2(Sap, a.y, p.y);
                fma2(San, a.x, n.x);  fma2(San, a.y, n.y);
            }
            float v = combine4(Sp, Sn, Sap, San);
            #pragma unroll
            for (int off = 16; off > 0; off >>= 1)
                v += __shfl_down_sync(0xFFFFFFFFu, v, off);
            if (lane == 0) acc += fmaxf(v + MARGIN, 0.0f);
        }
    }

    if (lane == 0) warp_part[wid] = acc;
    __syncthreads();
    if (tid == 0) {
        float total = 0.0f;
        #pragma unroll
        for (int w = 0; w < TPB / 32; w++) total += warp_part[w];
        atomicAdd(out, total);
    }
    #undef SLOT
}

extern "C" void kernel_launch(void* const* d_in, const int* in_sizes, int n_in,
                              void* d_out, int out_size) {
    const float* batch    = (const float*)d_in[0];
    const int*   triplets = (const int*)d_in[1];
    float* out = (float*)d_out;

    const int smem_bytes = PIPE_WARPS * NSTAGE * 3 * D * sizeof(float);  // 24576
    static bool attr_set = false;
    if (!attr_set) {
        cudaFuncSetAttribute(triplet_hybrid_kernel,
                             cudaFuncAttributeMaxDynamicSharedMemorySize, smem_bytes);
        attr_set = true;
    }

    zero_out_kernel<<<1, 32>>>(out);
    triplet_hybrid_kernel<<<GRID, TPB, smem_bytes>>>(batch, triplets, out);
}

// round 13
// speedup vs baseline: 1.3467x; 1.3467x over previous
#include <cuda_runtime.h>
#include <cstdint>

#define D          512
#define ROW_BYTES  2048
#define MARGIN     1.0f
#define NSTAGE     2
#define WPB        4                  // warps per block
#define TPB        (WPB * 32)
#define GRID       512
#define ITERS      8                  // triplets per warp: 512*4*8 = 16384
#define STAGE_TX   (3 * ROW_BYTES)    // 6144 bytes per triplet stage

__global__ void zero_out_kernel(float* out) {
    if (threadIdx.x == 0) out[0] = 0.0f;
}

__device__ __forceinline__ uint32_t smem_u32(const void* p) {
    return (uint32_t)__cvta_generic_to_shared(p);
}
__device__ __forceinline__ void mbar_init(uint32_t addr, uint32_t count) {
    asm volatile("mbarrier.init.shared::cta.b64 [%0], %1;" :: "r"(addr), "r"(count) : "memory");
}
__device__ __forceinline__ void mbar_expect_tx(uint32_t addr, uint32_t bytes) {
    asm volatile("mbarrier.arrive.expect_tx.shared::cta.b64 _, [%0], %1;"
                 :: "r"(addr), "r"(bytes) : "memory");
}
__device__ __forceinline__ void mbar_wait(uint32_t addr, uint32_t parity) {
    uint32_t done = 0;
    while (!done) {
        asm volatile(
            "{\n\t.reg .pred p;\n\t"
            "mbarrier.try_wait.parity.acquire.cta.shared::cta.b64 p, [%1], %2, 0x989680;\n\t"
            "selp.b32 %0, 1, 0, p;\n\t}"
            : "=r"(done) : "r"(addr), "r"(parity) : "memory");
    }
}
__device__ __forceinline__ void bulk_g2s(uint32_t dst_smem, const void* src_gmem,
                                         uint32_t bytes, uint32_t mbar) {
    asm volatile(
        "cp.async.bulk.shared::cluster.global.mbarrier::complete_tx::bytes "
        "[%0], [%1], %2, [%3];"
        :: "r"(dst_smem), "l"(src_gmem), "r"(bytes), "r"(mbar) : "memory");
}
__device__ __forceinline__ void fma2(unsigned long long& acc,
                                     unsigned long long a,
                                     unsigned long long b) {
    asm("fma.rn.f32x2 %0, %1, %2, %0;" : "+l"(acc) : "l"(a), "l"(b));
}
__device__ __forceinline__ float lo_f(unsigned long long v) {
    return __uint_as_float((unsigned)(v & 0xFFFFFFFFull));
}
__device__ __forceinline__ float hi_f(unsigned long long v) {
    return __uint_as_float((unsigned)(v >> 32));
}

__global__ void __launch_bounds__(TPB)
triplet_warp_pipe_kernel(const float* __restrict__ batch,
                         const int* __restrict__ triplets,
                         float* __restrict__ out) {
    // Dynamic smem: rows[WPB][NSTAGE][3][D] floats = 49152 bytes -> 4 CTA/SM.
    extern __shared__ __align__(1024) float rows[];
    __shared__ __align__(8) unsigned long long full_bar[WPB][NSTAGE];
    __shared__ int   idx_s[WPB][ITERS * 3];
    __shared__ float warp_part[WPB];

    const int tid  = threadIdx.x;
    const int lane = tid & 31;
    const int wid  = tid >> 5;
    const int wg   = blockIdx.x * WPB + wid;   // global warp id

    // This warp's 8 triplets (24 indices) -> smem.
    if (lane < ITERS * 3)
        idx_s[wid][lane] = triplets[wg * (ITERS * 3) + lane];

    if (tid < WPB * NSTAGE)
        mbar_init(smem_u32(&full_bar[tid >> 1][tid & 1]), 1);
    if (tid == 0)
        asm volatile("fence.proxy.async.shared::cta;" ::: "memory");
    __syncthreads();

    #define SLOT(w, s, r) (rows + (((w) * NSTAGE + (s)) * 3 + (r)) * D)

    // Prologue: lane 0 of each warp fills both of its stages.
    if (lane == 0) {
        #pragma unroll
        for (int s = 0; s < NSTAGE; s++) {
            const uint32_t fb = smem_u32(&full_bar[wid][s]);
            mbar_expect_tx(fb, STAGE_TX);
            #pragma unroll
            for (int r = 0; r < 3; r++) {
                const int idx = idx_s[wid][s * 3 + r];
                bulk_g2s(smem_u32(SLOT(wid, s, r)),
                         batch + (size_t)idx * D, ROW_BYTES, fb);
            }
        }
    }

    float acc = 0.0f;  // lane-0 accumulator

    #pragma unroll 1
    for (int i = 0; i < ITERS; i++) {
        const int s  = i & 1;
        const int ph = (i >> 1) & 1;

        mbar_wait(smem_u32(&full_bar[wid][s]), ph);

        const ulonglong2* A = reinterpret_cast<const ulonglong2*>(SLOT(wid, s, 0)) + lane;
        const ulonglong2* P = reinterpret_cast<const ulonglong2*>(SLOT(wid, s, 1)) + lane;
        const ulonglong2* N = reinterpret_cast<const ulonglong2*>(SLOT(wid, s, 2)) + lane;

        // d_ap - d_an = Sp - Sn - 2*Sap + 2*San  (Sum a^2 cancels)
        unsigned long long Sp = 0, Sn = 0, Sap = 0, San = 0;
        #pragma unroll
        for (int j = 0; j < 4; j++) {
            const ulonglong2 a = A[j * 32];
            const ulonglong2 p = P[j * 32];
            const ulonglong2 n = N[j * 32];
            fma2(Sp,  p.x, p.x);  fma2(Sp,  p.y, p.y);
            fma2(Sn,  n.x, n.x);  fma2(Sn,  n.y, n.y);
            fma2(Sap, a.x, p.x);  fma2(Sap, a.y, p.y);
            fma2(San, a.x, n.x);  fma2(San, a.y, n.y);
        }

        // All smem reads of stage s are done (data is in registers).
        // Refill NOW — before the shuffle reduction — so the next TMA round
        // starts ~80 cycles earlier each iteration.
        __syncwarp();
        const int j = i + NSTAGE;
        if (j < ITERS && lane == 0) {
            const uint32_t fb = smem_u32(&full_bar[wid][s]);
            mbar_expect_tx(fb, STAGE_TX);
            #pragma unroll
            for (int r = 0; r < 3; r++) {
                const int idx = idx_s[wid][j * 3 + r];
                bulk_g2s(smem_u32(SLOT(wid, s, r)),
                         batch + (size_t)idx * D, ROW_BYTES, fb);
            }
        }

        float v = (lo_f(Sp) + hi_f(Sp)) - (lo_f(Sn) + hi_f(Sn))
                + 2.0f * ((lo_f(San) + hi_f(San)) - (lo_f(Sap) + hi_f(Sap)));

        #pragma unroll
        for (int off = 16; off > 0; off >>= 1)
            v += __shfl_down_sync(0xFFFFFFFFu, v, off);

        if (lane == 0) acc += fmaxf(v + MARGIN, 0.0f);
    }

    if (lane == 0) warp_part[wid] = acc;
    __syncthreads();
    if (tid == 0) {
        float total = 0.0f;
        #pragma unroll
        for (int w = 0; w < WPB; w++) total += warp_part[w];
        atomicAdd(out, total);
    }
    #undef SLOT
}

extern "C" void kernel_launch(void* const* d_in, const int* in_sizes, int n_in,
                              void* d_out, int out_size) {
    const float* batch    = (const float*)d_in[0];
    const int*   triplets = (const int*)d_in[1];
    float* out = (float*)d_out;

    const int smem_bytes = WPB * NSTAGE * 3 * D * sizeof(float);  // 49152
    static bool attr_set = false;
    if (!attr_set) {
        cudaFuncSetAttribute(triplet_warp_pipe_kernel,
                             cudaFuncAttributeMaxDynamicSharedMemorySize, smem_bytes);
        attr_set = true;
    }

    zero_out_kernel<<<1, 32>>>(out);
    triplet_warp_pipe_kernel<<<GRID, TPB, smem_bytes>>>(batch, triplets, out);
}